// round 5
// baseline (speedup 1.0000x reference)
#include <cuda_runtime.h>
#include <cuda_fp16.h>
#include <math.h>

#define HW     65536      // 256*256
#define NB     8
#define CF_    64
#define HID_   512
#define KK     64
#define TP     128        // pixels per CTA
#define NT     128        // threads per CTA

// ---------------- scratch ----------------
__device__ float g_mask[(size_t)NB * KK * HW];   // (b,k,p)
__device__ float g_part[NB * KK * 5 * 512];      // per-CTA partials [b][k][comp][cta]
__device__ float g_wc[NB * 3 * KK];
__device__ float g_bkmean[NB * KK];
__device__ float g_bkmax[NB * KK];
// pre-split weights, hi/lo interleaved (uint2 = {hi half2, lo half2})
__device__ __align__(16) uint2 g1[32 * 512];     // [cpair][hid]
__device__ __align__(16) uint2 g2[256 * 64];     // [hidpair][k]

// ---------------- smem layout (bytes from dynamic base) ----------------
#define XS_PITCH 132
#define WP2      68                      // pitch in uint2 units (68 mod 16 == 4 -> LDS.64 conflict-free)
#define WCHUNK   (32 * WP2 * 8)          // 17408 B per chunk buffer
#define OFF_XS   0                       // 64 x 132 x 4 = 33792
#define OFF_W1   33792                   // 2 x 17408 = 34816
#define OFF_W2   (OFF_W1 + 2 * WCHUNK)   // 34816
#define OFF_B1   (OFF_W2 + 2 * WCHUNK)   // 2048
#define OFF_B2   (OFF_B1 + 2048)         // 256
#define OFF_IMG  (OFF_B2 + 256)          // 3 x 128 x 4 = 1536
#define SMEM_REQ (OFF_IMG + 1536)        // 107,264 B -> 2 CTAs/SM

// ---------------- helpers ----------------
__device__ __forceinline__ unsigned smem_u32(const void* p) {
    unsigned a;
    asm("{ .reg .u64 t; cvta.to.shared.u64 t, %1; cvt.u32.u64 %0, t; }" : "=r"(a) : "l"(p));
    return a;
}
#define CP16(dst, src) \
    asm volatile("cp.async.cg.shared.global [%0], [%1], 16;" :: "r"(dst), "l"(src) : "memory")
#define CP_COMMIT() asm volatile("cp.async.commit_group;" ::: "memory")
#define CP_WAIT(n)  asm volatile("cp.async.wait_group %0;" :: "n"(n) : "memory")

__device__ __forceinline__ void mma16816(float c[4], const unsigned a[4],
                                         unsigned b0, unsigned b1)
{
    asm volatile(
        "mma.sync.aligned.m16n8k16.row.col.f32.f16.f16.f32 "
        "{%0,%1,%2,%3},{%4,%5,%6,%7},{%8,%9},{%0,%1,%2,%3};\n"
        : "+f"(c[0]), "+f"(c[1]), "+f"(c[2]), "+f"(c[3])
        : "r"(a[0]), "r"(a[1]), "r"(a[2]), "r"(a[3]), "r"(b0), "r"(b1));
}
__device__ __forceinline__ void split2(float x, float y, unsigned &hi, unsigned &lo)
{
    __half hx = __float2half_rn(x), hy = __float2half_rn(y);
    __half lx = __float2half_rn(x - __half2float(hx));
    __half ly = __float2half_rn(y - __half2float(hy));
    __half2 h2 = __halves2half2(hx, hy), l2 = __halves2half2(lx, ly);
    hi = *reinterpret_cast<unsigned*>(&h2);
    lo = *reinterpret_cast<unsigned*>(&l2);
}

// ---------------------------------------------------------------
// prep: split weights into interleaved hi/lo half2 layouts
// ---------------------------------------------------------------
__global__ void k_prep(const float* __restrict__ w1, const float* __restrict__ w2)
{
    int i = blockIdx.x * blockDim.x + threadIdx.x;
    if (i < 32 * 512) {
        int cp = i >> 9, d = i & 511;
        unsigned hi, lo;
        split2(w1[(2 * cp) * HID_ + d], w1[(2 * cp + 1) * HID_ + d], hi, lo);
        g1[i] = make_uint2(hi, lo);
    } else if (i < 2 * 32 * 512) {
        int j = i - 32 * 512;
        int hp = j >> 6, k = j & 63;
        unsigned hi, lo;
        split2(w2[(2 * hp) * KK + k], w2[(2 * hp + 1) * KK + k], hi, lo);
        g2[j] = make_uint2(hi, lo);
    }
}

// stage one 64-hid chunk via cp.async (16B = 2 uint2 cols)
__device__ __forceinline__ void stage_chunk(unsigned sbase, int c, int buf, int tid)
{
    const unsigned w1d = sbase + OFF_W1 + (unsigned)buf * WCHUNK;
    const unsigned w2d = sbase + OFF_W2 + (unsigned)buf * WCHUNK;
#pragma unroll
    for (int i = tid; i < 1024; i += NT) {
        int cp = i >> 5, jj = i & 31;                 // 32 x 16B per row
        unsigned doff = (unsigned)(cp * WP2 + 2 * jj) * 8u;
        CP16(w1d + doff, g1 + cp * 512 + c * 64 + 2 * jj);
        CP16(w2d + doff, g2 + (c * 32 + cp) * 64 + 2 * jj);
    }
}

// ---------------------------------------------------------------
// K1: fused GEMM1(relu)+GEMM2+softmax+partial-reductions
// 128 threads / 128 pixels; warp = 32 pixels (2 m16 tiles)
// ---------------------------------------------------------------
__global__ __launch_bounds__(NT, 2)
void k_mask(const float* __restrict__ feat, const float* __restrict__ img,
            const float* __restrict__ b1, const float* __restrict__ b2)
{
    extern __shared__ __align__(16) char sm[];
    const unsigned sbase = smem_u32(sm);
    float* xs   = (float*)(sm + OFF_XS);
    float* b1s  = (float*)(sm + OFF_B1);
    float* b2s  = (float*)(sm + OFF_B2);
    float* imgs = (float*)(sm + OFF_IMG);

    const int tid  = threadIdx.x;
    const int warp = tid >> 5;
    const int lane = tid & 31;
    const int q    = lane & 3;
    const int g    = lane >> 2;
    const int nl   = g;

    const int b    = blockIdx.x >> 9;
    const int cta  = blockIdx.x & 511;
    const int p0   = cta * TP;

    stage_chunk(sbase, 0, 0, tid);
    CP_COMMIT();

    for (int i = tid; i < HID_; i += NT) b1s[i] = b1[i];
    if (tid < KK) b2s[tid] = b2[tid];

    // stage feat tile: 64 ch x 128 px
    {
        const float* fb = feat + (size_t)b * CF_ * HW + p0;
        for (int i = tid; i < CF_ * TP; i += NT) {
            int c = i >> 7, px = i & 127;
            xs[c * XS_PITCH + px] = fb[(size_t)c * HW + px];
        }
    }
    __syncthreads();

    // build A fragments for both tiles
    unsigned xah[2][4][4], xal[2][4][4];
#pragma unroll
    for (int t = 0; t < 2; t++) {
        const int prow = warp * 32 + t * 16 + g;
#pragma unroll
        for (int cc = 0; cc < 4; cc++) {
#pragma unroll
            for (int hlf = 0; hlf < 2; hlf++) {
                int c0i = cc * 16 + hlf * 8 + 2 * q;
                float x0 = xs[c0i * XS_PITCH + prow];
                float x1 = xs[(c0i + 1) * XS_PITCH + prow];
                float x2 = xs[c0i * XS_PITCH + prow + 8];
                float x3 = xs[(c0i + 1) * XS_PITCH + prow + 8];
                split2(x0, x1, xah[t][cc][hlf * 2 + 0], xal[t][cc][hlf * 2 + 0]);
                split2(x2, x3, xah[t][cc][hlf * 2 + 1], xal[t][cc][hlf * 2 + 1]);
            }
        }
    }

    // logits accumulators, init with b2
    float acc[2][8][4];
#pragma unroll
    for (int kn = 0; kn < 8; kn++) {
        float bb0 = b2s[kn * 8 + 2 * q], bb1 = b2s[kn * 8 + 2 * q + 1];
#pragma unroll
        for (int t = 0; t < 2; t++) {
            acc[t][kn][0] = bb0; acc[t][kn][1] = bb1;
            acc[t][kn][2] = bb0; acc[t][kn][3] = bb1;
        }
    }

    // ---- 8 double-buffered 64-hid chunks ----
    for (int c = 0; c < 8; c++) {
        if (c < 7) { stage_chunk(sbase, c + 1, (c + 1) & 1, tid); CP_COMMIT(); CP_WAIT(1); }
        else       { CP_WAIT(0); }
        __syncthreads();

        const uint2* w1p = (const uint2*)(sm + OFF_W1 + (c & 1) * WCHUNK);
        const uint2* w2p = (const uint2*)(sm + OFF_W2 + (c & 1) * WCHUNK);

#pragma unroll
        for (int hc = 0; hc < 4; hc++) {
            const int h0 = c * 64 + hc * 16;
            // two accumulator sets per (t,nc): cc{0,1} -> za, cc{2,3} -> zb
            float za[2][2][4], zb[2][2][4];
#pragma unroll
            for (int nc = 0; nc < 2; nc++) {
                float bb0 = b1s[h0 + nc * 8 + 2 * q];
                float bb1 = b1s[h0 + nc * 8 + 2 * q + 1];
#pragma unroll
                for (int t = 0; t < 2; t++) {
                    za[t][nc][0] = bb0; za[t][nc][1] = bb1;
                    za[t][nc][2] = bb0; za[t][nc][3] = bb1;
                    zb[t][nc][0] = 0.f; zb[t][nc][1] = 0.f;
                    zb[t][nc][2] = 0.f; zb[t][nc][3] = 0.f;
                }
            }
            // GEMM1
#pragma unroll
            for (int cc = 0; cc < 4; cc++) {
                float (*zz)[2][4] = (cc < 2) ? za : zb;
#pragma unroll
                for (int nc = 0; nc < 2; nc++) {
                    int col = hc * 16 + nc * 8 + nl;
                    uint2 B0 = w1p[(cc * 8 + q) * WP2 + col];
                    uint2 B1 = w1p[(cc * 8 + q + 4) * WP2 + col];
                    mma16816(zz[0][nc], xah[0][cc], B0.x, B1.x);
                    mma16816(zz[0][nc], xah[0][cc], B0.y, B1.y);
                    mma16816(zz[0][nc], xal[0][cc], B0.x, B1.x);
                    mma16816(zz[1][nc], xah[1][cc], B0.x, B1.x);
                    mma16816(zz[1][nc], xah[1][cc], B0.y, B1.y);
                    mma16816(zz[1][nc], xal[1][cc], B0.x, B1.x);
                }
            }
            // merge + ReLU + split + repack C->A
            unsigned Ah[2][4], Al[2][4];
#pragma unroll
            for (int t = 0; t < 2; t++) {
                float v00 = fmaxf(za[t][0][0] + zb[t][0][0], 0.f);
                float v01 = fmaxf(za[t][0][1] + zb[t][0][1], 0.f);
                float v02 = fmaxf(za[t][0][2] + zb[t][0][2], 0.f);
                float v03 = fmaxf(za[t][0][3] + zb[t][0][3], 0.f);
                float v10 = fmaxf(za[t][1][0] + zb[t][1][0], 0.f);
                float v11 = fmaxf(za[t][1][1] + zb[t][1][1], 0.f);
                float v12 = fmaxf(za[t][1][2] + zb[t][1][2], 0.f);
                float v13 = fmaxf(za[t][1][3] + zb[t][1][3], 0.f);
                split2(v00, v01, Ah[t][0], Al[t][0]);
                split2(v02, v03, Ah[t][1], Al[t][1]);
                split2(v10, v11, Ah[t][2], Al[t][2]);
                split2(v12, v13, Ah[t][3], Al[t][3]);
            }
            // GEMM2
#pragma unroll
            for (int kn = 0; kn < 8; kn++) {
                uint2 B0 = w2p[(hc * 8 + q) * WP2 + kn * 8 + nl];
                uint2 B1 = w2p[(hc * 8 + q + 4) * WP2 + kn * 8 + nl];
                mma16816(acc[0][kn], Ah[0], B0.x, B1.x);
                mma16816(acc[0][kn], Ah[0], B0.y, B1.y);
                mma16816(acc[0][kn], Al[0], B0.x, B1.x);
                mma16816(acc[1][kn], Ah[1], B0.x, B1.x);
                mma16816(acc[1][kn], Ah[1], B0.y, B1.y);
                mma16816(acc[1][kn], Al[1], B0.x, B1.x);
            }
        }
        __syncthreads();
    }

    // ---- softmax + stage mask into xs ----
#pragma unroll
    for (int t = 0; t < 2; t++) {
        const int prow = warp * 32 + t * 16 + g;
        float mA = -1e30f, mB = -1e30f;
#pragma unroll
        for (int kn = 0; kn < 8; kn++) {
            mA = fmaxf(mA, fmaxf(acc[t][kn][0], acc[t][kn][1]));
            mB = fmaxf(mB, fmaxf(acc[t][kn][2], acc[t][kn][3]));
        }
        mA = fmaxf(mA, __shfl_xor_sync(0xffffffffu, mA, 1));
        mA = fmaxf(mA, __shfl_xor_sync(0xffffffffu, mA, 2));
        mB = fmaxf(mB, __shfl_xor_sync(0xffffffffu, mB, 1));
        mB = fmaxf(mB, __shfl_xor_sync(0xffffffffu, mB, 2));
        float sA = 0.f, sB = 0.f;
#pragma unroll
        for (int kn = 0; kn < 8; kn++) {
            acc[t][kn][0] = __expf(acc[t][kn][0] - mA); sA += acc[t][kn][0];
            acc[t][kn][1] = __expf(acc[t][kn][1] - mA); sA += acc[t][kn][1];
            acc[t][kn][2] = __expf(acc[t][kn][2] - mB); sB += acc[t][kn][2];
            acc[t][kn][3] = __expf(acc[t][kn][3] - mB); sB += acc[t][kn][3];
        }
        sA += __shfl_xor_sync(0xffffffffu, sA, 1);
        sA += __shfl_xor_sync(0xffffffffu, sA, 2);
        sB += __shfl_xor_sync(0xffffffffu, sB, 1);
        sB += __shfl_xor_sync(0xffffffffu, sB, 2);
        const float invA = 1.0f / sA, invB = 1.0f / sB;
#pragma unroll
        for (int kn = 0; kn < 8; kn++) {
            int c0 = kn * 8 + 2 * q;
            xs[c0 * XS_PITCH + prow]           = acc[t][kn][0] * invA;
            xs[(c0 + 1) * XS_PITCH + prow]     = acc[t][kn][1] * invA;
            xs[c0 * XS_PITCH + prow + 8]       = acc[t][kn][2] * invB;
            xs[(c0 + 1) * XS_PITCH + prow + 8] = acc[t][kn][3] * invB;
        }
    }
    // stage img tile
    for (int i = tid; i < 3 * TP; i += NT)
        imgs[i] = img[(size_t)b * 3 * HW + (size_t)(i >> 7) * HW + p0 + (i & 127)];
    __syncthreads();

    // coalesced mask store
    {
        float* gm = g_mask + (size_t)b * KK * HW + p0;
        for (int i = tid; i < KK * TP; i += NT) {
            int k = i >> 7, px = i & 127;
            gm[(size_t)k * HW + px] = xs[k * XS_PITCH + px];
        }
    }

    // per-CTA partial reductions: thread = (k, half)
    {
        const int k    = tid & 63;
        const int half = tid >> 6;            // 0: px 0..63, 1: px 64..127
        const int px0  = half * 64;
        float s = 0.f, mx = -1e30f, c0 = 0.f, c1 = 0.f, c2 = 0.f;
        const float* mrow = xs + k * XS_PITCH + px0;
#pragma unroll 4
        for (int j = 0; j < 64; j++) {
            float mv = mrow[j];
            s += mv;
            mx = fmaxf(mx, mv);
            c0 = fmaf(mv, imgs[px0 + j],       c0);
            c1 = fmaf(mv, imgs[128 + px0 + j], c1);
            c2 = fmaf(mv, imgs[256 + px0 + j], c2);
        }
        __syncthreads();          // xs reads done (b1s about to be reused)
        if (half == 1) {
            b1s[k * 5 + 0] = s;  b1s[k * 5 + 1] = mx;
            b1s[k * 5 + 2] = c0; b1s[k * 5 + 3] = c1; b1s[k * 5 + 4] = c2;
        }
        __syncthreads();
        if (half == 0) {
            float* gp = g_part + ((size_t)(b * KK + k) * 5) * 512 + cta;
            gp[0 * 512] = s  + b1s[k * 5 + 0];
            gp[1 * 512] = fmaxf(mx, b1s[k * 5 + 1]);
            gp[2 * 512] = c0 + b1s[k * 5 + 2];
            gp[3 * 512] = c1 + b1s[k * 5 + 3];
            gp[4 * 512] = c2 + b1s[k * 5 + 4];
        }
    }
}

// ---------------------------------------------------------------
// K2: fold 512 per-CTA partials per (b,k)
// ---------------------------------------------------------------
__global__ __launch_bounds__(256)
void k_reduce2()
{
    __shared__ float smr[256];
    const int bk = blockIdx.x;
    const int b = bk >> 6, k = bk & 63;
    const int t = threadIdx.x;
    const float* gp = g_part + (size_t)bk * 5 * 512;

    float r[5];
#pragma unroll
    for (int comp = 0; comp < 5; comp++) {
        float v;
        if (comp == 1) {
            v = fmaxf(gp[comp * 512 + t], gp[comp * 512 + t + 256]);
            smr[t] = v; __syncthreads();
            for (int st = 128; st > 0; st >>= 1) {
                if (t < st) smr[t] = fmaxf(smr[t], smr[t + st]);
                __syncthreads();
            }
        } else {
            v = gp[comp * 512 + t] + gp[comp * 512 + t + 256];
            smr[t] = v; __syncthreads();
            for (int st = 128; st > 0; st >>= 1) {
                if (t < st) smr[t] += smr[t + st];
                __syncthreads();
            }
        }
        r[comp] = smr[0]; __syncthreads();
    }
    if (t == 0) {
        const float invhw = 1.0f / (float)HW;
        g_bkmean[bk] = r[0] * invhw;
        g_bkmax[bk]  = r[1];
        g_wc[(b * 3 + 0) * KK + k] = r[2] * invhw;
        g_wc[(b * 3 + 1) * KK + k] = r[3] * invhw;
        g_wc[(b * 3 + 2) * KK + k] = r[4] * invhw;
    }
}

// ---------------------------------------------------------------
// K3: scalar outputs
// ---------------------------------------------------------------
__global__ void k_final(float* __restrict__ out)
{
    __shared__ float smr[512];
    __shared__ float bmean[NB], bstd[NB];
    const int t = threadIdx.x;

    smr[t] = g_bkmax[t]; __syncthreads();
    for (int st = 256; st > 0; st >>= 1) { if (t < st) smr[t] += smr[t + st]; __syncthreads(); }
    if (t == 0) out[(size_t)NB * 3 * HW] = smr[0] * (1.0f / 512.0f);
    __syncthreads();

    const float mv = g_bkmean[t];
    smr[t] = mv; __syncthreads();
    if (t < NB) {
        float sbm = 0.f;
        for (int k = 0; k < KK; k++) sbm += smr[t * KK + k];
        bmean[t] = sbm * (1.0f / KK);
    }
    __syncthreads();
    const float d = mv - bmean[t >> 6];
    smr[t] = d * d; __syncthreads();
    if (t < NB) {
        float sbm = 0.f;
        for (int k = 0; k < KK; k++) sbm += smr[t * KK + k];
        bstd[t] = sqrtf(sbm / (float)(KK - 1));
    }
    __syncthreads();
    if (t == 0) {
        float sbm = 0.f;
        for (int bb = 0; bb < NB; bb++) sbm += bstd[bb];
        out[(size_t)NB * 3 * HW + 1] = sbm * (1.0f / NB);
    }
}

// ---------------------------------------------------------------
// K4: transformed_img[b,c,p] = sum_k mask[b,k,p] * wc[b,c,k]
// ---------------------------------------------------------------
__global__ __launch_bounds__(256)
void k_transform(float* __restrict__ out)
{
    __shared__ float wcs[3 * KK];
    const int b = blockIdx.x >> 8;
    const int p = ((blockIdx.x & 255) << 8) + threadIdx.x;
    if (threadIdx.x < 3 * KK) wcs[threadIdx.x] = g_wc[b * 3 * KK + threadIdx.x];
    __syncthreads();

    const float* gm = g_mask + (size_t)b * KK * HW + p;
    float o0 = 0.f, o1 = 0.f, o2 = 0.f;
#pragma unroll
    for (int k = 0; k < KK; k++) {
        const float mv = __ldcs(&gm[(size_t)k * HW]);
        o0 = fmaf(mv, wcs[k],          o0);
        o1 = fmaf(mv, wcs[KK + k],     o1);
        o2 = fmaf(mv, wcs[2 * KK + k], o2);
    }
    out[((size_t)b * 3 + 0) * HW + p] = o0;
    out[((size_t)b * 3 + 1) * HW + p] = o1;
    out[((size_t)b * 3 + 2) * HW + p] = o2;
}

// ---------------------------------------------------------------
extern "C" void kernel_launch(void* const* d_in, const int* in_sizes, int n_in,
                              void* d_out, int out_size)
{
    const float* img  = (const float*)d_in[0];
    const float* feat = (const float*)d_in[1];
    // d_in[2] = coord_map (unused)
    const float* w1 = (const float*)d_in[3];
    const float* b1 = (const float*)d_in[4];
    const float* w2 = (const float*)d_in[5];
    const float* b2 = (const float*)d_in[6];
    float* out = (float*)d_out;

    cudaFuncSetAttribute(k_mask, cudaFuncAttributeMaxDynamicSharedMemorySize, SMEM_REQ);

    k_prep<<<128, 256>>>(w1, w2);
    k_mask<<<NB * (HW / TP), NT, SMEM_REQ>>>(feat, img, b1, b2);
    k_reduce2<<<NB * KK, 256>>>();
    k_final<<<1, 512>>>(out);
    k_transform<<<NB * (HW / 256), 256>>>(out);
}

// round 6
// speedup vs baseline: 1.1624x; 1.1624x over previous
#include <cuda_runtime.h>
#include <cuda_fp16.h>
#include <math.h>

#define HW     65536      // 256*256
#define NB     8
#define CF_    64
#define HID_   512
#define KK     64
#define TP     128        // pixels per CTA
#define NT     128        // threads per CTA

// ---------------- scratch ----------------
__device__ float g_mask[(size_t)NB * KK * HW];   // (b,k,p)
__device__ float g_part[NB * KK * 5 * 512];      // per-CTA partials [b][k][comp][cta]
__device__ float g_wc[NB * 3 * KK];
__device__ float g_bkmean[NB * KK];
__device__ float g_bkmax[NB * KK];
// pre-split weights, hi/lo interleaved (uint2 = {hi half2, lo half2})
__device__ __align__(16) uint2 g1[32 * 512];     // [cpair][hid]
__device__ __align__(16) uint2 g2[256 * 64];     // [hidpair][k]

// ---------------- smem layout (bytes from dynamic base) ----------------
#define XS_PITCH 132
#define WP2      68                      // pitch in uint2 units (conflict-free LDS.64)
#define WCHUNK   (32 * WP2 * 8)          // 17408 B per chunk buffer
#define OFF_XS   0                       // 64 x 132 x 4 = 33792
#define OFF_W1   33792                   // 2 x 17408
#define OFF_W2   (OFF_W1 + 2 * WCHUNK)
#define OFF_B1   (OFF_W2 + 2 * WCHUNK)   // 2048
#define OFF_B2   (OFF_B1 + 2048)         // 256
#define OFF_IMG  (OFF_B2 + 256)          // 1536
#define SMEM_REQ (OFF_IMG + 1536)        // 107,264 B -> 2 CTAs/SM

// ---------------- helpers ----------------
__device__ __forceinline__ unsigned smem_u32(const void* p) {
    unsigned a;
    asm("{ .reg .u64 t; cvta.to.shared.u64 t, %1; cvt.u32.u64 %0, t; }" : "=r"(a) : "l"(p));
    return a;
}
#define CP16(dst, src) \
    asm volatile("cp.async.cg.shared.global [%0], [%1], 16;" :: "r"(dst), "l"(src) : "memory")
#define CP_COMMIT() asm volatile("cp.async.commit_group;" ::: "memory")
#define CP_WAIT(n)  asm volatile("cp.async.wait_group %0;" :: "n"(n) : "memory")

__device__ __forceinline__ void mma16816(float c[4], const unsigned a[4],
                                         unsigned b0, unsigned b1)
{
    asm volatile(
        "mma.sync.aligned.m16n8k16.row.col.f32.f16.f16.f32 "
        "{%0,%1,%2,%3},{%4,%5,%6,%7},{%8,%9},{%0,%1,%2,%3};\n"
        : "+f"(c[0]), "+f"(c[1]), "+f"(c[2]), "+f"(c[3])
        : "r"(a[0]), "r"(a[1]), "r"(a[2]), "r"(a[3]), "r"(b0), "r"(b1));
}
__device__ __forceinline__ void split2(float x, float y, unsigned &hi, unsigned &lo)
{
    __half hx = __float2half_rn(x), hy = __float2half_rn(y);
    __half lx = __float2half_rn(x - __half2float(hx));
    __half ly = __float2half_rn(y - __half2float(hy));
    __half2 h2 = __halves2half2(hx, hy), l2 = __halves2half2(lx, ly);
    hi = *reinterpret_cast<unsigned*>(&h2);
    lo = *reinterpret_cast<unsigned*>(&l2);
}
__device__ __forceinline__ unsigned pack2(float x, float y)
{
    __half2 h2 = __floats2half2_rn(x, y);
    return *reinterpret_cast<unsigned*>(&h2);
}

// ---------------------------------------------------------------
// prep: split weights into interleaved hi/lo half2 layouts
// ---------------------------------------------------------------
__global__ void k_prep(const float* __restrict__ w1, const float* __restrict__ w2)
{
    int i = blockIdx.x * blockDim.x + threadIdx.x;
    if (i < 32 * 512) {
        int cp = i >> 9, d = i & 511;
        unsigned hi, lo;
        split2(w1[(2 * cp) * HID_ + d], w1[(2 * cp + 1) * HID_ + d], hi, lo);
        g1[i] = make_uint2(hi, lo);
    } else if (i < 2 * 32 * 512) {
        int j = i - 32 * 512;
        int hp = j >> 6, k = j & 63;
        unsigned hi, lo;
        split2(w2[(2 * hp) * KK + k], w2[(2 * hp + 1) * KK + k], hi, lo);
        g2[j] = make_uint2(hi, lo);
    }
}

// stage one 64-hid chunk via cp.async (16B = 2 uint2 cols)
__device__ __forceinline__ void stage_chunk(unsigned sbase, int c, int buf, int tid)
{
    const unsigned w1d = sbase + OFF_W1 + (unsigned)buf * WCHUNK;
    const unsigned w2d = sbase + OFF_W2 + (unsigned)buf * WCHUNK;
#pragma unroll
    for (int i = tid; i < 1024; i += NT) {
        int cp = i >> 5, jj = i & 31;
        unsigned doff = (unsigned)(cp * WP2 + 2 * jj) * 8u;
        CP16(w1d + doff, g1 + cp * 512 + c * 64 + 2 * jj);
        CP16(w2d + doff, g2 + (c * 32 + cp) * 64 + 2 * jj);
    }
}

// ---------------------------------------------------------------
// K1: fused GEMM1(relu,split3)+GEMM2(split2)+softmax+partial-reductions
// 128 threads / 128 pixels; warp = 32 pixels (2 m16 tiles)
// ---------------------------------------------------------------
__global__ __launch_bounds__(NT, 2)
void k_mask(const float* __restrict__ feat, const float* __restrict__ img,
            const float* __restrict__ b1, const float* __restrict__ b2)
{
    extern __shared__ __align__(16) char sm[];
    const unsigned sbase = smem_u32(sm);
    float* xs   = (float*)(sm + OFF_XS);
    float* b1s  = (float*)(sm + OFF_B1);
    float* b2s  = (float*)(sm + OFF_B2);
    float* imgs = (float*)(sm + OFF_IMG);

    const int tid  = threadIdx.x;
    const int warp = tid >> 5;
    const int lane = tid & 31;
    const int q    = lane & 3;
    const int g    = lane >> 2;
    const int nl   = g;

    const int b    = blockIdx.x >> 9;
    const int cta  = blockIdx.x & 511;
    const int p0   = cta * TP;

    stage_chunk(sbase, 0, 0, tid);
    CP_COMMIT();

    for (int i = tid; i < HID_; i += NT) b1s[i] = b1[i];
    if (tid < KK) b2s[tid] = b2[tid];

    // stage feat tile: 64 ch x 128 px
    {
        const float* fb = feat + (size_t)b * CF_ * HW + p0;
        for (int i = tid; i < CF_ * TP; i += NT) {
            int c = i >> 7, px = i & 127;
            xs[c * XS_PITCH + px] = fb[(size_t)c * HW + px];
        }
    }
    __syncthreads();

    // build A fragments for both tiles
    unsigned xah[2][4][4], xal[2][4][4];
#pragma unroll
    for (int t = 0; t < 2; t++) {
        const int prow = warp * 32 + t * 16 + g;
#pragma unroll
        for (int cc = 0; cc < 4; cc++) {
#pragma unroll
            for (int hlf = 0; hlf < 2; hlf++) {
                int c0i = cc * 16 + hlf * 8 + 2 * q;
                float x0 = xs[c0i * XS_PITCH + prow];
                float x1 = xs[(c0i + 1) * XS_PITCH + prow];
                float x2 = xs[c0i * XS_PITCH + prow + 8];
                float x3 = xs[(c0i + 1) * XS_PITCH + prow + 8];
                split2(x0, x1, xah[t][cc][hlf * 2 + 0], xal[t][cc][hlf * 2 + 0]);
                split2(x2, x3, xah[t][cc][hlf * 2 + 1], xal[t][cc][hlf * 2 + 1]);
            }
        }
    }

    // logits accumulators, init with b2
    float acc[2][8][4];
#pragma unroll
    for (int kn = 0; kn < 8; kn++) {
        float bb0 = b2s[kn * 8 + 2 * q], bb1 = b2s[kn * 8 + 2 * q + 1];
#pragma unroll
        for (int t = 0; t < 2; t++) {
            acc[t][kn][0] = bb0; acc[t][kn][1] = bb1;
            acc[t][kn][2] = bb0; acc[t][kn][3] = bb1;
        }
    }

    // ---- 8 double-buffered 64-hid chunks ----
    for (int c = 0; c < 8; c++) {
        if (c < 7) { stage_chunk(sbase, c + 1, (c + 1) & 1, tid); CP_COMMIT(); CP_WAIT(1); }
        else       { CP_WAIT(0); }
        __syncthreads();

        const uint2* w1p = (const uint2*)(sm + OFF_W1 + (c & 1) * WCHUNK);
        const uint2* w2p = (const uint2*)(sm + OFF_W2 + (c & 1) * WCHUNK);

#pragma unroll
        for (int hc = 0; hc < 4; hc++) {
            const int h0 = c * 64 + hc * 16;
            float z[2][2][4];
#pragma unroll
            for (int nc = 0; nc < 2; nc++) {
                float bb0 = b1s[h0 + nc * 8 + 2 * q];
                float bb1 = b1s[h0 + nc * 8 + 2 * q + 1];
#pragma unroll
                for (int t = 0; t < 2; t++) {
                    z[t][nc][0] = bb0; z[t][nc][1] = bb1;
                    z[t][nc][2] = bb0; z[t][nc][3] = bb1;
                }
            }
            // GEMM1 (split-3)
#pragma unroll
            for (int cc = 0; cc < 4; cc++) {
#pragma unroll
                for (int nc = 0; nc < 2; nc++) {
                    int col = hc * 16 + nc * 8 + nl;
                    uint2 B0 = w1p[(cc * 8 + q) * WP2 + col];
                    uint2 B1 = w1p[(cc * 8 + q + 4) * WP2 + col];
                    mma16816(z[0][nc], xah[0][cc], B0.x, B1.x);
                    mma16816(z[0][nc], xah[0][cc], B0.y, B1.y);
                    mma16816(z[0][nc], xal[0][cc], B0.x, B1.x);
                    mma16816(z[1][nc], xah[1][cc], B0.x, B1.x);
                    mma16816(z[1][nc], xah[1][cc], B0.y, B1.y);
                    mma16816(z[1][nc], xal[1][cc], B0.x, B1.x);
                }
            }
            // ReLU + pack C->A (fp16 only — GEMM2 is split-2 on the weight side)
            unsigned Ah[2][4];
#pragma unroll
            for (int t = 0; t < 2; t++) {
                Ah[t][0] = pack2(fmaxf(z[t][0][0], 0.f), fmaxf(z[t][0][1], 0.f));
                Ah[t][1] = pack2(fmaxf(z[t][0][2], 0.f), fmaxf(z[t][0][3], 0.f));
                Ah[t][2] = pack2(fmaxf(z[t][1][0], 0.f), fmaxf(z[t][1][1], 0.f));
                Ah[t][3] = pack2(fmaxf(z[t][1][2], 0.f), fmaxf(z[t][1][3], 0.f));
            }
            // GEMM2 (split-2: Ah*Bhi + Ah*Blo)
#pragma unroll
            for (int kn = 0; kn < 8; kn++) {
                uint2 B0 = w2p[(hc * 8 + q) * WP2 + kn * 8 + nl];
                uint2 B1 = w2p[(hc * 8 + q + 4) * WP2 + kn * 8 + nl];
                mma16816(acc[0][kn], Ah[0], B0.x, B1.x);
                mma16816(acc[0][kn], Ah[0], B0.y, B1.y);
                mma16816(acc[1][kn], Ah[1], B0.x, B1.x);
                mma16816(acc[1][kn], Ah[1], B0.y, B1.y);
            }
        }
        __syncthreads();
    }

    // ---- softmax + stage mask into xs ----
#pragma unroll
    for (int t = 0; t < 2; t++) {
        const int prow = warp * 32 + t * 16 + g;
        float mA = -1e30f, mB = -1e30f;
#pragma unroll
        for (int kn = 0; kn < 8; kn++) {
            mA = fmaxf(mA, fmaxf(acc[t][kn][0], acc[t][kn][1]));
            mB = fmaxf(mB, fmaxf(acc[t][kn][2], acc[t][kn][3]));
        }
        mA = fmaxf(mA, __shfl_xor_sync(0xffffffffu, mA, 1));
        mA = fmaxf(mA, __shfl_xor_sync(0xffffffffu, mA, 2));
        mB = fmaxf(mB, __shfl_xor_sync(0xffffffffu, mB, 1));
        mB = fmaxf(mB, __shfl_xor_sync(0xffffffffu, mB, 2));
        float sA = 0.f, sB = 0.f;
#pragma unroll
        for (int kn = 0; kn < 8; kn++) {
            acc[t][kn][0] = __expf(acc[t][kn][0] - mA); sA += acc[t][kn][0];
            acc[t][kn][1] = __expf(acc[t][kn][1] - mA); sA += acc[t][kn][1];
            acc[t][kn][2] = __expf(acc[t][kn][2] - mB); sB += acc[t][kn][2];
            acc[t][kn][3] = __expf(acc[t][kn][3] - mB); sB += acc[t][kn][3];
        }
        sA += __shfl_xor_sync(0xffffffffu, sA, 1);
        sA += __shfl_xor_sync(0xffffffffu, sA, 2);
        sB += __shfl_xor_sync(0xffffffffu, sB, 1);
        sB += __shfl_xor_sync(0xffffffffu, sB, 2);
        const float invA = 1.0f / sA, invB = 1.0f / sB;
#pragma unroll
        for (int kn = 0; kn < 8; kn++) {
            int c0 = kn * 8 + 2 * q;
            xs[c0 * XS_PITCH + prow]           = acc[t][kn][0] * invA;
            xs[(c0 + 1) * XS_PITCH + prow]     = acc[t][kn][1] * invA;
            xs[c0 * XS_PITCH + prow + 8]       = acc[t][kn][2] * invB;
            xs[(c0 + 1) * XS_PITCH + prow + 8] = acc[t][kn][3] * invB;
        }
    }
    // stage img tile
    for (int i = tid; i < 3 * TP; i += NT)
        imgs[i] = img[(size_t)b * 3 * HW + (size_t)(i >> 7) * HW + p0 + (i & 127)];
    __syncthreads();

    // coalesced mask store
    {
        float* gm = g_mask + (size_t)b * KK * HW + p0;
        for (int i = tid; i < KK * TP; i += NT) {
            int k = i >> 7, px = i & 127;
            gm[(size_t)k * HW + px] = xs[k * XS_PITCH + px];
        }
    }

    // per-CTA partial reductions: thread = (k, half)
    {
        const int k    = tid & 63;
        const int half = tid >> 6;
        const int px0  = half * 64;
        float s = 0.f, mx = -1e30f, c0 = 0.f, c1 = 0.f, c2 = 0.f;
        const float* mrow = xs + k * XS_PITCH + px0;
#pragma unroll 4
        for (int j = 0; j < 64; j++) {
            float mv = mrow[j];
            s += mv;
            mx = fmaxf(mx, mv);
            c0 = fmaf(mv, imgs[px0 + j],       c0);
            c1 = fmaf(mv, imgs[128 + px0 + j], c1);
            c2 = fmaf(mv, imgs[256 + px0 + j], c2);
        }
        __syncthreads();
        if (half == 1) {
            b1s[k * 5 + 0] = s;  b1s[k * 5 + 1] = mx;
            b1s[k * 5 + 2] = c0; b1s[k * 5 + 3] = c1; b1s[k * 5 + 4] = c2;
        }
        __syncthreads();
        if (half == 0) {
            float* gp = g_part + ((size_t)(b * KK + k) * 5) * 512 + cta;
            gp[0 * 512] = s  + b1s[k * 5 + 0];
            gp[1 * 512] = fmaxf(mx, b1s[k * 5 + 1]);
            gp[2 * 512] = c0 + b1s[k * 5 + 2];
            gp[3 * 512] = c1 + b1s[k * 5 + 3];
            gp[4 * 512] = c2 + b1s[k * 5 + 4];
        }
    }
}

// ---------------------------------------------------------------
// K2: fold 512 per-CTA partials per (b,k)
// ---------------------------------------------------------------
__global__ __launch_bounds__(256)
void k_reduce2()
{
    __shared__ float smr[256];
    const int bk = blockIdx.x;
    const int b = bk >> 6, k = bk & 63;
    const int t = threadIdx.x;
    const float* gp = g_part + (size_t)bk * 5 * 512;

    float r[5];
#pragma unroll
    for (int comp = 0; comp < 5; comp++) {
        float v;
        if (comp == 1) {
            v = fmaxf(gp[comp * 512 + t], gp[comp * 512 + t + 256]);
            smr[t] = v; __syncthreads();
            for (int st = 128; st > 0; st >>= 1) {
                if (t < st) smr[t] = fmaxf(smr[t], smr[t + st]);
                __syncthreads();
            }
        } else {
            v = gp[comp * 512 + t] + gp[comp * 512 + t + 256];
            smr[t] = v; __syncthreads();
            for (int st = 128; st > 0; st >>= 1) {
                if (t < st) smr[t] += smr[t + st];
                __syncthreads();
            }
        }
        r[comp] = smr[0]; __syncthreads();
    }
    if (t == 0) {
        const float invhw = 1.0f / (float)HW;
        g_bkmean[bk] = r[0] * invhw;
        g_bkmax[bk]  = r[1];
        g_wc[(b * 3 + 0) * KK + k] = r[2] * invhw;
        g_wc[(b * 3 + 1) * KK + k] = r[3] * invhw;
        g_wc[(b * 3 + 2) * KK + k] = r[4] * invhw;
    }
}

// ---------------------------------------------------------------
// K3: scalar outputs
// ---------------------------------------------------------------
__global__ void k_final(float* __restrict__ out)
{
    __shared__ float smr[512];
    __shared__ float bmean[NB], bstd[NB];
    const int t = threadIdx.x;

    smr[t] = g_bkmax[t]; __syncthreads();
    for (int st = 256; st > 0; st >>= 1) { if (t < st) smr[t] += smr[t + st]; __syncthreads(); }
    if (t == 0) out[(size_t)NB * 3 * HW] = smr[0] * (1.0f / 512.0f);
    __syncthreads();

    const float mv = g_bkmean[t];
    smr[t] = mv; __syncthreads();
    if (t < NB) {
        float sbm = 0.f;
        for (int k = 0; k < KK; k++) sbm += smr[t * KK + k];
        bmean[t] = sbm * (1.0f / KK);
    }
    __syncthreads();
    const float d = mv - bmean[t >> 6];
    smr[t] = d * d; __syncthreads();
    if (t < NB) {
        float sbm = 0.f;
        for (int k = 0; k < KK; k++) sbm += smr[t * KK + k];
        bstd[t] = sqrtf(sbm / (float)(KK - 1));
    }
    __syncthreads();
    if (t == 0) {
        float sbm = 0.f;
        for (int bb = 0; bb < NB; bb++) sbm += bstd[bb];
        out[(size_t)NB * 3 * HW + 1] = sbm * (1.0f / NB);
    }
}

// ---------------------------------------------------------------
// K4: transformed_img[b,c,p] = sum_k mask[b,k,p] * wc[b,c,k]
// ---------------------------------------------------------------
__global__ __launch_bounds__(256)
void k_transform(float* __restrict__ out)
{
    __shared__ float wcs[3 * KK];
    const int b = blockIdx.x >> 8;
    const int p = ((blockIdx.x & 255) << 8) + threadIdx.x;
    if (threadIdx.x < 3 * KK) wcs[threadIdx.x] = g_wc[b * 3 * KK + threadIdx.x];
    __syncthreads();

    const float* gm = g_mask + (size_t)b * KK * HW + p;
    float o0 = 0.f, o1 = 0.f, o2 = 0.f;
#pragma unroll
    for (int k = 0; k < KK; k++) {
        const float mv = __ldcs(&gm[(size_t)k * HW]);
        o0 = fmaf(mv, wcs[k],          o0);
        o1 = fmaf(mv, wcs[KK + k],     o1);
        o2 = fmaf(mv, wcs[2 * KK + k], o2);
    }
    out[((size_t)b * 3 + 0) * HW + p] = o0;
    out[((size_t)b * 3 + 1) * HW + p] = o1;
    out[((size_t)b * 3 + 2) * HW + p] = o2;
}

// ---------------------------------------------------------------
extern "C" void kernel_launch(void* const* d_in, const int* in_sizes, int n_in,
                              void* d_out, int out_size)
{
    const float* img  = (const float*)d_in[0];
    const float* feat = (const float*)d_in[1];
    // d_in[2] = coord_map (unused)
    const float* w1 = (const float*)d_in[3];
    const float* b1 = (const float*)d_in[4];
    const float* w2 = (const float*)d_in[5];
    const float* b2 = (const float*)d_in[6];
    float* out = (float*)d_out;

    cudaFuncSetAttribute(k_mask, cudaFuncAttributeMaxDynamicSharedMemorySize, SMEM_REQ);

    k_prep<<<128, 256>>>(w1, w2);
    k_mask<<<NB * (HW / TP), NT, SMEM_REQ>>>(feat, img, b1, b2);
    k_reduce2<<<NB * KK, 256>>>();
    k_final<<<1, 512>>>(out);
    k_transform<<<NB * (HW / 256), 256>>>(out);
}

// round 8
// speedup vs baseline: 1.2878x; 1.1079x over previous
#include <cuda_runtime.h>
#include <cuda_fp16.h>
#include <math.h>

#define HW     65536      // 256*256
#define NB     8
#define CF_    64
#define HID_   512
#define KK     64
#define TP     128        // pixels per CTA
#define NT     128        // threads per CTA

// ---------------- scratch ----------------
__device__ float g_mask[(size_t)NB * KK * HW];   // (b,k,p)
__device__ float g_part[NB * KK * 5 * 512];      // per-CTA partials [b][k][comp][cta]
__device__ float g_wc[NB * 3 * KK];
__device__ float g_bkmean[NB * KK];
__device__ float g_bkmax[NB * KK];
// pre-split weights, hi/lo interleaved (uint2 = {hi half2, lo half2})
__device__ __align__(16) uint2 g1[32 * 512];     // [cpair][hid]
__device__ __align__(16) uint2 g2[256 * 64];     // [hidpair][k]

// ---------------- smem layout (bytes from dynamic base) ----------------
#define XS_PITCH 132
#define WP2      68                      // pitch in uint2 units (conflict-free LDS.64)
#define WCHUNK   (32 * WP2 * 8)          // 17408 B per chunk buffer
#define OFF_XS   0                       // 64 x 132 x 4 = 33792
#define OFF_W1   33792                   // 2 x 17408
#define OFF_W2   (OFF_W1 + 2 * WCHUNK)
#define OFF_B1   (OFF_W2 + 2 * WCHUNK)   // 2048
#define OFF_B2   (OFF_B1 + 2048)         // 256
#define OFF_IMG  (OFF_B2 + 256)          // 1536
#define SMEM_REQ (OFF_IMG + 1536)        // 107,264 B -> 2 CTAs/SM

// ---------------- helpers ----------------
__device__ __forceinline__ unsigned smem_u32(const void* p) {
    unsigned a;
    asm("{ .reg .u64 t; cvta.to.shared.u64 t, %1; cvt.u32.u64 %0, t; }" : "=r"(a) : "l"(p));
    return a;
}
#define CP16(dst, src) \
    asm volatile("cp.async.cg.shared.global [%0], [%1], 16;" :: "r"(dst), "l"(src) : "memory")
#define CP_COMMIT() asm volatile("cp.async.commit_group;" ::: "memory")
#define CP_WAIT(n)  asm volatile("cp.async.wait_group %0;" :: "n"(n) : "memory")

__device__ __forceinline__ void mma16816(float c[4], const unsigned a[4],
                                         unsigned b0, unsigned b1)
{
    asm volatile(
        "mma.sync.aligned.m16n8k16.row.col.f32.f16.f16.f32 "
        "{%0,%1,%2,%3},{%4,%5,%6,%7},{%8,%9},{%0,%1,%2,%3};\n"
        : "+f"(c[0]), "+f"(c[1]), "+f"(c[2]), "+f"(c[3])
        : "r"(a[0]), "r"(a[1]), "r"(a[2]), "r"(a[3]), "r"(b0), "r"(b1));
}
__device__ __forceinline__ void split2(float x, float y, unsigned &hi, unsigned &lo)
{
    __half hx = __float2half_rn(x), hy = __float2half_rn(y);
    __half lx = __float2half_rn(x - __half2float(hx));
    __half ly = __float2half_rn(y - __half2float(hy));
    __half2 h2 = __halves2half2(hx, hy), l2 = __halves2half2(lx, ly);
    hi = *reinterpret_cast<unsigned*>(&h2);
    lo = *reinterpret_cast<unsigned*>(&l2);
}
__device__ __forceinline__ unsigned pack2(float x, float y)
{
    __half2 h2 = __floats2half2_rn(x, y);
    return *reinterpret_cast<unsigned*>(&h2);
}

// ---------------------------------------------------------------
// prep: split weights into interleaved hi/lo half2 layouts
// ---------------------------------------------------------------
__global__ void k_prep(const float* __restrict__ w1, const float* __restrict__ w2)
{
    int i = blockIdx.x * blockDim.x + threadIdx.x;
    if (i < 32 * 512) {
        int cp = i >> 9, d = i & 511;
        unsigned hi, lo;
        split2(w1[(2 * cp) * HID_ + d], w1[(2 * cp + 1) * HID_ + d], hi, lo);
        g1[i] = make_uint2(hi, lo);
    } else if (i < 2 * 32 * 512) {
        int j = i - 32 * 512;
        int hp = j >> 6, k = j & 63;
        unsigned hi, lo;
        split2(w2[(2 * hp) * KK + k], w2[(2 * hp + 1) * KK + k], hi, lo);
        g2[j] = make_uint2(hi, lo);
    }
}

// stage one 64-hid chunk via cp.async (16B = 2 uint2 cols)
__device__ __forceinline__ void stage_chunk(unsigned sbase, int c, int buf, int tid)
{
    const unsigned w1d = sbase + OFF_W1 + (unsigned)buf * WCHUNK;
    const unsigned w2d = sbase + OFF_W2 + (unsigned)buf * WCHUNK;
#pragma unroll
    for (int i = tid; i < 1024; i += NT) {
        int cp = i >> 5, jj = i & 31;
        unsigned doff = (unsigned)(cp * WP2 + 2 * jj) * 8u;
        CP16(w1d + doff, g1 + cp * 512 + c * 64 + 2 * jj);
        CP16(w2d + doff, g2 + (c * 32 + cp) * 64 + 2 * jj);
    }
}

// ---------------------------------------------------------------
// K1: fused GEMM1(relu,split2)+GEMM2(split2)+softmax+partial-reductions
// 128 threads / 128 pixels; warp = 32 pixels (2 m16 tiles)
// ---------------------------------------------------------------
__global__ __launch_bounds__(NT, 2)
void k_mask(const float* __restrict__ feat, const float* __restrict__ img,
            const float* __restrict__ b1, const float* __restrict__ b2)
{
    extern __shared__ __align__(16) char sm[];
    const unsigned sbase = smem_u32(sm);
    float* xs   = (float*)(sm + OFF_XS);
    float* b1s  = (float*)(sm + OFF_B1);
    float* b2s  = (float*)(sm + OFF_B2);
    float* imgs = (float*)(sm + OFF_IMG);

    const int tid  = threadIdx.x;
    const int warp = tid >> 5;
    const int lane = tid & 31;
    const int q    = lane & 3;
    const int g    = lane >> 2;
    const int nl   = g;

    const int b    = blockIdx.x >> 9;
    const int cta  = blockIdx.x & 511;
    const int p0   = cta * TP;

    stage_chunk(sbase, 0, 0, tid);
    CP_COMMIT();

    for (int i = tid; i < HID_; i += NT) b1s[i] = b1[i];
    if (tid < KK) b2s[tid] = b2[tid];

    // stage feat tile: 64 ch x 128 px
    {
        const float* fb = feat + (size_t)b * CF_ * HW + p0;
        for (int i = tid; i < CF_ * TP; i += NT) {
            int c = i >> 7, px = i & 127;
            xs[c * XS_PITCH + px] = fb[(size_t)c * HW + px];
        }
    }
    __syncthreads();

    // build A fragments for both tiles (fp16 hi only — GEMM1 is split-2 on weights)
    unsigned xah[2][4][4];
#pragma unroll
    for (int t = 0; t < 2; t++) {
        const int prow = warp * 32 + t * 16 + g;
#pragma unroll
        for (int cc = 0; cc < 4; cc++) {
#pragma unroll
            for (int hlf = 0; hlf < 2; hlf++) {
                int c0i = cc * 16 + hlf * 8 + 2 * q;
                float x0 = xs[c0i * XS_PITCH + prow];
                float x1 = xs[(c0i + 1) * XS_PITCH + prow];
                float x2 = xs[c0i * XS_PITCH + prow + 8];
                float x3 = xs[(c0i + 1) * XS_PITCH + prow + 8];
                xah[t][cc][hlf * 2 + 0] = pack2(x0, x1);
                xah[t][cc][hlf * 2 + 1] = pack2(x2, x3);
            }
        }
    }

    // logits accumulators, init with b2
    float acc[2][8][4];
#pragma unroll
    for (int kn = 0; kn < 8; kn++) {
        float bb0 = b2s[kn * 8 + 2 * q], bb1 = b2s[kn * 8 + 2 * q + 1];
#pragma unroll
        for (int t = 0; t < 2; t++) {
            acc[t][kn][0] = bb0; acc[t][kn][1] = bb1;
            acc[t][kn][2] = bb0; acc[t][kn][3] = bb1;
        }
    }

    // ---- 8 double-buffered 64-hid chunks ----
    for (int c = 0; c < 8; c++) {
        if (c < 7) { stage_chunk(sbase, c + 1, (c + 1) & 1, tid); CP_COMMIT(); CP_WAIT(1); }
        else       { CP_WAIT(0); }
        __syncthreads();

        const uint2* w1p = (const uint2*)(sm + OFF_W1 + (c & 1) * WCHUNK);
        const uint2* w2p = (const uint2*)(sm + OFF_W2 + (c & 1) * WCHUNK);

#pragma unroll
        for (int hc = 0; hc < 4; hc++) {
            const int h0 = c * 64 + hc * 16;
            float z[2][2][4];
#pragma unroll
            for (int nc = 0; nc < 2; nc++) {
                float bb0 = b1s[h0 + nc * 8 + 2 * q];
                float bb1 = b1s[h0 + nc * 8 + 2 * q + 1];
#pragma unroll
                for (int t = 0; t < 2; t++) {
                    z[t][nc][0] = bb0; z[t][nc][1] = bb1;
                    z[t][nc][2] = bb0; z[t][nc][3] = bb1;
                }
            }
            // GEMM1 (split-2: xah*Bhi + xah*Blo)
#pragma unroll
            for (int cc = 0; cc < 4; cc++) {
#pragma unroll
                for (int nc = 0; nc < 2; nc++) {
                    int col = hc * 16 + nc * 8 + nl;
                    uint2 B0 = w1p[(cc * 8 + q) * WP2 + col];
                    uint2 B1 = w1p[(cc * 8 + q + 4) * WP2 + col];
                    mma16816(z[0][nc], xah[0][cc], B0.x, B1.x);
                    mma16816(z[0][nc], xah[0][cc], B0.y, B1.y);
                    mma16816(z[1][nc], xah[1][cc], B0.x, B1.x);
                    mma16816(z[1][nc], xah[1][cc], B0.y, B1.y);
                }
            }
            // ReLU + pack C->A
            unsigned Ah[2][4];
#pragma unroll
            for (int t = 0; t < 2; t++) {
                Ah[t][0] = pack2(fmaxf(z[t][0][0], 0.f), fmaxf(z[t][0][1], 0.f));
                Ah[t][1] = pack2(fmaxf(z[t][0][2], 0.f), fmaxf(z[t][0][3], 0.f));
                Ah[t][2] = pack2(fmaxf(z[t][1][0], 0.f), fmaxf(z[t][1][1], 0.f));
                Ah[t][3] = pack2(fmaxf(z[t][1][2], 0.f), fmaxf(z[t][1][3], 0.f));
            }
            // GEMM2 (split-2: Ah*Bhi + Ah*Blo)
#pragma unroll
            for (int kn = 0; kn < 8; kn++) {
                uint2 B0 = w2p[(hc * 8 + q) * WP2 + kn * 8 + nl];
                uint2 B1 = w2p[(hc * 8 + q + 4) * WP2 + kn * 8 + nl];
                mma16816(acc[0][kn], Ah[0], B0.x, B1.x);
                mma16816(acc[0][kn], Ah[0], B0.y, B1.y);
                mma16816(acc[1][kn], Ah[1], B0.x, B1.x);
                mma16816(acc[1][kn], Ah[1], B0.y, B1.y);
            }
        }
        __syncthreads();
    }

    // ---- softmax + stage mask into xs ----
#pragma unroll
    for (int t = 0; t < 2; t++) {
        const int prow = warp * 32 + t * 16 + g;
        float mA = -1e30f, mB = -1e30f;
#pragma unroll
        for (int kn = 0; kn < 8; kn++) {
            mA = fmaxf(mA, fmaxf(acc[t][kn][0], acc[t][kn][1]));
            mB = fmaxf(mB, fmaxf(acc[t][kn][2], acc[t][kn][3]));
        }
        mA = fmaxf(mA, __shfl_xor_sync(0xffffffffu, mA, 1));
        mA = fmaxf(mA, __shfl_xor_sync(0xffffffffu, mA, 2));
        mB = fmaxf(mB, __shfl_xor_sync(0xffffffffu, mB, 1));
        mB = fmaxf(mB, __shfl_xor_sync(0xffffffffu, mB, 2));
        float sA = 0.f, sB = 0.f;
#pragma unroll
        for (int kn = 0; kn < 8; kn++) {
            acc[t][kn][0] = __expf(acc[t][kn][0] - mA); sA += acc[t][kn][0];
            acc[t][kn][1] = __expf(acc[t][kn][1] - mA); sA += acc[t][kn][1];
            acc[t][kn][2] = __expf(acc[t][kn][2] - mB); sB += acc[t][kn][2];
            acc[t][kn][3] = __expf(acc[t][kn][3] - mB); sB += acc[t][kn][3];
        }
        sA += __shfl_xor_sync(0xffffffffu, sA, 1);
        sA += __shfl_xor_sync(0xffffffffu, sA, 2);
        sB += __shfl_xor_sync(0xffffffffu, sB, 1);
        sB += __shfl_xor_sync(0xffffffffu, sB, 2);
        const float invA = 1.0f / sA, invB = 1.0f / sB;
#pragma unroll
        for (int kn = 0; kn < 8; kn++) {
            int c0 = kn * 8 + 2 * q;
            xs[c0 * XS_PITCH + prow]           = acc[t][kn][0] * invA;
            xs[(c0 + 1) * XS_PITCH + prow]     = acc[t][kn][1] * invA;
            xs[c0 * XS_PITCH + prow + 8]       = acc[t][kn][2] * invB;
            xs[(c0 + 1) * XS_PITCH + prow + 8] = acc[t][kn][3] * invB;
        }
    }
    // stage img tile
    for (int i = tid; i < 3 * TP; i += NT)
        imgs[i] = img[(size_t)b * 3 * HW + (size_t)(i >> 7) * HW + p0 + (i & 127)];
    __syncthreads();

    // coalesced mask store
    {
        float* gm = g_mask + (size_t)b * KK * HW + p0;
        for (int i = tid; i < KK * TP; i += NT) {
            int k = i >> 7, px = i & 127;
            gm[(size_t)k * HW + px] = xs[k * XS_PITCH + px];
        }
    }

    // per-CTA partial reductions: thread = (k, half)
    {
        const int k    = tid & 63;
        const int half = tid >> 6;
        const int px0  = half * 64;
        float s = 0.f, mx = -1e30f, c0 = 0.f, c1 = 0.f, c2 = 0.f;
        const float* mrow = xs + k * XS_PITCH + px0;
#pragma unroll 4
        for (int j = 0; j < 64; j++) {
            float mv = mrow[j];
            s += mv;
            mx = fmaxf(mx, mv);
            c0 = fmaf(mv, imgs[px0 + j],       c0);
            c1 = fmaf(mv, imgs[128 + px0 + j], c1);
            c2 = fmaf(mv, imgs[256 + px0 + j], c2);
        }
        __syncthreads();
        if (half == 1) {
            b1s[k * 5 + 0] = s;  b1s[k * 5 + 1] = mx;
            b1s[k * 5 + 2] = c0; b1s[k * 5 + 3] = c1; b1s[k * 5 + 4] = c2;
        }
        __syncthreads();
        if (half == 0) {
            float* gp = g_part + ((size_t)(b * KK + k) * 5) * 512 + cta;
            gp[0 * 512] = s  + b1s[k * 5 + 0];
            gp[1 * 512] = fmaxf(mx, b1s[k * 5 + 1]);
            gp[2 * 512] = c0 + b1s[k * 5 + 2];
            gp[3 * 512] = c1 + b1s[k * 5 + 3];
            gp[4 * 512] = c2 + b1s[k * 5 + 4];
        }
    }
}

// ---------------------------------------------------------------
// K2: fold 512 per-CTA partials per (b,k)
// ---------------------------------------------------------------
__global__ __launch_bounds__(256)
void k_reduce2()
{
    __shared__ float smr[256];
    const int bk = blockIdx.x;
    const int b = bk >> 6, k = bk & 63;
    const int t = threadIdx.x;
    const float* gp = g_part + (size_t)bk * 5 * 512;

    float r[5];
#pragma unroll
    for (int comp = 0; comp < 5; comp++) {
        float v;
        if (comp == 1) {
            v = fmaxf(gp[comp * 512 + t], gp[comp * 512 + t + 256]);
            smr[t] = v; __syncthreads();
            for (int st = 128; st > 0; st >>= 1) {
                if (t < st) smr[t] = fmaxf(smr[t], smr[t + st]);
                __syncthreads();
            }
        } else {
            v = gp[comp * 512 + t] + gp[comp * 512 + t + 256];
            smr[t] = v; __syncthreads();
            for (int st = 128; st > 0; st >>= 1) {
                if (t < st) smr[t] += smr[t + st];
                __syncthreads();
            }
        }
        r[comp] = smr[0]; __syncthreads();
    }
    if (t == 0) {
        const float invhw = 1.0f / (float)HW;
        g_bkmean[bk] = r[0] * invhw;
        g_bkmax[bk]  = r[1];
        g_wc[(b * 3 + 0) * KK + k] = r[2] * invhw;
        g_wc[(b * 3 + 1) * KK + k] = r[3] * invhw;
        g_wc[(b * 3 + 2) * KK + k] = r[4] * invhw;
    }
}

// ---------------------------------------------------------------
// K3: scalar outputs
// ---------------------------------------------------------------
__global__ void k_final(float* __restrict__ out)
{
    __shared__ float smr[512];
    __shared__ float bmean[NB], bstd[NB];
    const int t = threadIdx.x;

    smr[t] = g_bkmax[t]; __syncthreads();
    for (int st = 256; st > 0; st >>= 1) { if (t < st) smr[t] += smr[t + st]; __syncthreads(); }
    if (t == 0) out[(size_t)NB * 3 * HW] = smr[0] * (1.0f / 512.0f);
    __syncthreads();

    const float mv = g_bkmean[t];
    smr[t] = mv; __syncthreads();
    if (t < NB) {
        float sbm = 0.f;
        for (int k = 0; k < KK; k++) sbm += smr[t * KK + k];
        bmean[t] = sbm * (1.0f / KK);
    }
    __syncthreads();
    const float d = mv - bmean[t >> 6];
    smr[t] = d * d; __syncthreads();
    if (t < NB) {
        float sbm = 0.f;
        for (int k = 0; k < KK; k++) sbm += smr[t * KK + k];
        bstd[t] = sqrtf(sbm / (float)(KK - 1));
    }
    __syncthreads();
    if (t == 0) {
        float sbm = 0.f;
        for (int bb = 0; bb < NB; bb++) sbm += bstd[bb];
        out[(size_t)NB * 3 * HW + 1] = sbm * (1.0f / NB);
    }
}

// ---------------------------------------------------------------
// K4: transformed_img[b,c,p] = sum_k mask[b,k,p] * wc[b,c,k]
// ---------------------------------------------------------------
__global__ __launch_bounds__(256)
void k_transform(float* __restrict__ out)
{
    __shared__ float wcs[3 * KK];
    const int b = blockIdx.x >> 8;
    const int p = ((blockIdx.x & 255) << 8) + threadIdx.x;
    if (threadIdx.x < 3 * KK) wcs[threadIdx.x] = g_wc[b * 3 * KK + threadIdx.x];
    __syncthreads();

    const float* gm = g_mask + (size_t)b * KK * HW + p;
    float o0 = 0.f, o1 = 0.f, o2 = 0.f;
#pragma unroll
    for (int k = 0; k < KK; k++) {
        const float mv = __ldcs(&gm[(size_t)k * HW]);
        o0 = fmaf(mv, wcs[k],          o0);
        o1 = fmaf(mv, wcs[KK + k],     o1);
        o2 = fmaf(mv, wcs[2 * KK + k], o2);
    }
    out[((size_t)b * 3 + 0) * HW + p] = o0;
    out[((size_t)b * 3 + 1) * HW + p] = o1;
    out[((size_t)b * 3 + 2) * HW + p] = o2;
}

// ---------------------------------------------------------------
extern "C" void kernel_launch(void* const* d_in, const int* in_sizes, int n_in,
                              void* d_out, int out_size)
{
    const float* img  = (const float*)d_in[0];
    const float* feat = (const float*)d_in[1];
    // d_in[2] = coord_map (unused)
    const float* w1 = (const float*)d_in[3];
    const float* b1 = (const float*)d_in[4];
    const float* w2 = (const float*)d_in[5];
    const float* b2 = (const float*)d_in[6];
    float* out = (float*)d_out;

    cudaFuncSetAttribute(k_mask, cudaFuncAttributeMaxDynamicSharedMemorySize, SMEM_REQ);

    k_prep<<<128, 256>>>(w1, w2);
    k_mask<<<NB * (HW / TP), NT, SMEM_REQ>>>(feat, img, b1, b2);
    k_reduce2<<<NB * KK, 256>>>();
    k_final<<<1, 512>>>(out);
    k_transform<<<NB * (HW / 256), 256>>>(out);
}

// round 9
// speedup vs baseline: 1.5189x; 1.1795x over previous
#include <cuda_runtime.h>
#include <cuda_fp16.h>
#include <math.h>

#define HW     65536      // 256*256
#define NB     8
#define CF_    64
#define HID_   512
#define KK     64
#define TP     128        // pixels per CTA
#define NT     128        // threads per CTA
#define NCH    16         // 16 chunks of 32 hid

// ---------------- scratch ----------------
__device__ float g_mask[(size_t)NB * KK * HW];   // (b,k,p)
__device__ float g_part[NB * KK * 5 * 512];      // per-CTA partials [b][k][comp][cta]
__device__ float g_wc[NB * 3 * KK];
__device__ float g_bkmean[NB * KK];
__device__ float g_bkmax[NB * KK];
// pre-split weights, hi/lo interleaved (uint2 = {hi half2, lo half2})
__device__ __align__(16) uint2 g1[32 * 512];     // [cpair][hid]
__device__ __align__(16) uint2 g2[256 * 64];     // [hidpair][k]

// ---------------- smem layout (bytes from dynamic base) ----------------
#define XS_PITCH 136                     // u32 units, conflict-free
#define MS_PITCH 132                     // float units (mask tile)
#define WP1      36                      // w1 pitch (uint2): 32 cols + pad
#define WP2K     68                      // w2 pitch (uint2): 64 cols + pad
#define W1BUF    (32 * WP1 * 8)          // 9216 B
#define W2BUF    (16 * WP2K * 8)         // 8704 B
#define OFF_XS   0                       // 32 x 136 x 4 = 17408 (feat as half2 pairs)
#define OFF_W1   17408                   // 2 x 9216 = 18432
#define OFF_W2   (OFF_W1 + 2 * W1BUF)    // 35840; 2 x 8704 = 17408
#define OFF_B1   (OFF_W2 + 2 * W2BUF)    // 53248; 2048
#define OFF_B2   (OFF_B1 + 2048)         // 55296; 256
#define OFF_IMG  (OFF_B2 + 256)          // 55552; 1536
#define OFF_MS   OFF_W1                  // mask tile reuses weight buffers (33792 <= 35840)
#define SMEM_REQ 57344                   // -> 3 CTAs/SM by smem

// ---------------- helpers ----------------
__device__ __forceinline__ unsigned smem_u32(const void* p) {
    unsigned a;
    asm("{ .reg .u64 t; cvta.to.shared.u64 t, %1; cvt.u32.u64 %0, t; }" : "=r"(a) : "l"(p));
    return a;
}
#define CP16(dst, src) \
    asm volatile("cp.async.cg.shared.global [%0], [%1], 16;" :: "r"(dst), "l"(src) : "memory")
#define CP_COMMIT() asm volatile("cp.async.commit_group;" ::: "memory")
#define CP_WAIT(n)  asm volatile("cp.async.wait_group %0;" :: "n"(n) : "memory")

__device__ __forceinline__ void mma16816(float c[4], const unsigned a[4],
                                         unsigned b0, unsigned b1)
{
    asm volatile(
        "mma.sync.aligned.m16n8k16.row.col.f32.f16.f16.f32 "
        "{%0,%1,%2,%3},{%4,%5,%6,%7},{%8,%9},{%0,%1,%2,%3};\n"
        : "+f"(c[0]), "+f"(c[1]), "+f"(c[2]), "+f"(c[3])
        : "r"(a[0]), "r"(a[1]), "r"(a[2]), "r"(a[3]), "r"(b0), "r"(b1));
}
__device__ __forceinline__ void split2(float x, float y, unsigned &hi, unsigned &lo)
{
    __half hx = __float2half_rn(x), hy = __float2half_rn(y);
    __half lx = __float2half_rn(x - __half2float(hx));
    __half ly = __float2half_rn(y - __half2float(hy));
    __half2 h2 = __halves2half2(hx, hy), l2 = __halves2half2(lx, ly);
    hi = *reinterpret_cast<unsigned*>(&h2);
    lo = *reinterpret_cast<unsigned*>(&l2);
}
__device__ __forceinline__ unsigned pack2(float x, float y)
{
    __half2 h2 = __floats2half2_rn(x, y);
    return *reinterpret_cast<unsigned*>(&h2);
}

// ---------------------------------------------------------------
// prep: split weights into interleaved hi/lo half2 layouts
// ---------------------------------------------------------------
__global__ void k_prep(const float* __restrict__ w1, const float* __restrict__ w2)
{
    int i = blockIdx.x * blockDim.x + threadIdx.x;
    if (i < 32 * 512) {
        int cp = i >> 9, d = i & 511;
        unsigned hi, lo;
        split2(w1[(2 * cp) * HID_ + d], w1[(2 * cp + 1) * HID_ + d], hi, lo);
        g1[i] = make_uint2(hi, lo);
    } else if (i < 2 * 32 * 512) {
        int j = i - 32 * 512;
        int hp = j >> 6, k = j & 63;
        unsigned hi, lo;
        split2(w2[(2 * hp) * KK + k], w2[(2 * hp + 1) * KK + k], hi, lo);
        g2[j] = make_uint2(hi, lo);
    }
}

// stage one 32-hid chunk via cp.async
__device__ __forceinline__ void stage_chunk(unsigned sbase, int c, int buf, int tid)
{
    const unsigned w1d = sbase + OFF_W1 + (unsigned)buf * W1BUF;
    const unsigned w2d = sbase + OFF_W2 + (unsigned)buf * W2BUF;
#pragma unroll
    for (int i = tid; i < 512; i += NT) {
        int r1 = i >> 4, j1 = i & 15;     // w1: 32 rows x 16 segs (2 uint2 each)
        CP16(w1d + (unsigned)(r1 * WP1 + 2 * j1) * 8u, g1 + r1 * 512 + c * 32 + 2 * j1);
        int r2 = i >> 5, j2 = i & 31;     // w2: 16 rows x 32 segs
        CP16(w2d + (unsigned)(r2 * WP2K + 2 * j2) * 8u, g2 + (c * 16 + r2) * 64 + 2 * j2);
    }
}

// ---------------------------------------------------------------
// K1: fused GEMM1(relu,split2)+GEMM2(split2)+softmax+partial-reductions
// 128 threads / 128 pixels; warp = 32 pixels (2 m16 tiles); 3 CTAs/SM
// ---------------------------------------------------------------
__global__ __launch_bounds__(NT, 3)
void k_mask(const float* __restrict__ feat, const float* __restrict__ img,
            const float* __restrict__ b1, const float* __restrict__ b2)
{
    extern __shared__ __align__(16) char sm[];
    const unsigned sbase = smem_u32(sm);
    unsigned* xsu = (unsigned*)(sm + OFF_XS);
    float* ms   = (float*)(sm + OFF_MS);
    float* b1s  = (float*)(sm + OFF_B1);
    float* b2s  = (float*)(sm + OFF_B2);
    float* imgs = (float*)(sm + OFF_IMG);

    const int tid  = threadIdx.x;
    const int warp = tid >> 5;
    const int lane = tid & 31;
    const int q    = lane & 3;
    const int g    = lane >> 2;
    const int nl   = g;

    const int b    = blockIdx.x >> 9;
    const int cta  = blockIdx.x & 511;
    const int p0   = cta * TP;

    stage_chunk(sbase, 0, 0, tid);
    CP_COMMIT();

    for (int i = tid; i < HID_; i += NT) b1s[i] = b1[i];
    if (tid < KK) b2s[tid] = b2[tid];

    // stage feat tile as channel-paired half2: [32 cpair][128 px]
    {
        const float* fb = feat + (size_t)b * CF_ * HW + p0;
        for (int i = tid; i < 32 * TP; i += NT) {
            int cp = i >> 7, px = i & 127;
            float v0 = fb[(size_t)(2 * cp) * HW + px];
            float v1 = fb[(size_t)(2 * cp + 1) * HW + px];
            xsu[cp * XS_PITCH + px] = pack2(v0, v1);
        }
    }
    __syncthreads();

    // build A fragments (single LDS.32 each; layout matches R8 semantics)
    unsigned xah[2][4][4];
#pragma unroll
    for (int t = 0; t < 2; t++) {
        const int prow = warp * 32 + t * 16 + g;
#pragma unroll
        for (int cc = 0; cc < 4; cc++) {
#pragma unroll
            for (int hlf = 0; hlf < 2; hlf++) {
                int cp = cc * 8 + hlf * 4 + q;
                xah[t][cc][hlf * 2 + 0] = xsu[cp * XS_PITCH + prow];
                xah[t][cc][hlf * 2 + 1] = xsu[cp * XS_PITCH + prow + 8];
            }
        }
    }

    // logits accumulators, init with b2
    float acc[2][8][4];
#pragma unroll
    for (int kn = 0; kn < 8; kn++) {
        float bb0 = b2s[kn * 8 + 2 * q], bb1 = b2s[kn * 8 + 2 * q + 1];
#pragma unroll
        for (int t = 0; t < 2; t++) {
            acc[t][kn][0] = bb0; acc[t][kn][1] = bb1;
            acc[t][kn][2] = bb0; acc[t][kn][3] = bb1;
        }
    }

    // ---- 16 double-buffered 32-hid chunks ----
    for (int c = 0; c < NCH; c++) {
        if (c < NCH - 1) { stage_chunk(sbase, c + 1, (c + 1) & 1, tid); CP_COMMIT(); CP_WAIT(1); }
        else             { CP_WAIT(0); }
        __syncthreads();

        const uint2* w1p = (const uint2*)(sm + OFF_W1 + (c & 1) * W1BUF);
        const uint2* w2p = (const uint2*)(sm + OFF_W2 + (c & 1) * W2BUF);

#pragma unroll
        for (int hc = 0; hc < 2; hc++) {
            const int h0 = c * 32 + hc * 16;
            float z[2][2][4];
#pragma unroll
            for (int nc = 0; nc < 2; nc++) {
                float bb0 = b1s[h0 + nc * 8 + 2 * q];
                float bb1 = b1s[h0 + nc * 8 + 2 * q + 1];
#pragma unroll
                for (int t = 0; t < 2; t++) {
                    z[t][nc][0] = bb0; z[t][nc][1] = bb1;
                    z[t][nc][2] = bb0; z[t][nc][3] = bb1;
                }
            }
            // GEMM1 (split-2: xah*Bhi + xah*Blo)
#pragma unroll
            for (int cc = 0; cc < 4; cc++) {
#pragma unroll
                for (int nc = 0; nc < 2; nc++) {
                    int col = hc * 16 + nc * 8 + nl;
                    uint2 B0 = w1p[(cc * 8 + q) * WP1 + col];
                    uint2 B1 = w1p[(cc * 8 + q + 4) * WP1 + col];
                    mma16816(z[0][nc], xah[0][cc], B0.x, B1.x);
                    mma16816(z[0][nc], xah[0][cc], B0.y, B1.y);
                    mma16816(z[1][nc], xah[1][cc], B0.x, B1.x);
                    mma16816(z[1][nc], xah[1][cc], B0.y, B1.y);
                }
            }
            // ReLU + pack C->A
            unsigned Ah[2][4];
#pragma unroll
            for (int t = 0; t < 2; t++) {
                Ah[t][0] = pack2(fmaxf(z[t][0][0], 0.f), fmaxf(z[t][0][1], 0.f));
                Ah[t][1] = pack2(fmaxf(z[t][0][2], 0.f), fmaxf(z[t][0][3], 0.f));
                Ah[t][2] = pack2(fmaxf(z[t][1][0], 0.f), fmaxf(z[t][1][1], 0.f));
                Ah[t][3] = pack2(fmaxf(z[t][1][2], 0.f), fmaxf(z[t][1][3], 0.f));
            }
            // GEMM2 (split-2: Ah*Bhi + Ah*Blo)
#pragma unroll
            for (int kn = 0; kn < 8; kn++) {
                uint2 B0 = w2p[(hc * 8 + q) * WP2K + kn * 8 + nl];
                uint2 B1 = w2p[(hc * 8 + q + 4) * WP2K + kn * 8 + nl];
                mma16816(acc[0][kn], Ah[0], B0.x, B1.x);
                mma16816(acc[0][kn], Ah[0], B0.y, B1.y);
                mma16816(acc[1][kn], Ah[1], B0.x, B1.x);
                mma16816(acc[1][kn], Ah[1], B0.y, B1.y);
            }
        }
        __syncthreads();
    }

    // ---- softmax + stage mask into ms (freed weight region) ----
#pragma unroll
    for (int t = 0; t < 2; t++) {
        const int prow = warp * 32 + t * 16 + g;
        float mA = -1e30f, mB = -1e30f;
#pragma unroll
        for (int kn = 0; kn < 8; kn++) {
            mA = fmaxf(mA, fmaxf(acc[t][kn][0], acc[t][kn][1]));
            mB = fmaxf(mB, fmaxf(acc[t][kn][2], acc[t][kn][3]));
        }
        mA = fmaxf(mA, __shfl_xor_sync(0xffffffffu, mA, 1));
        mA = fmaxf(mA, __shfl_xor_sync(0xffffffffu, mA, 2));
        mB = fmaxf(mB, __shfl_xor_sync(0xffffffffu, mB, 1));
        mB = fmaxf(mB, __shfl_xor_sync(0xffffffffu, mB, 2));
        float sA = 0.f, sB = 0.f;
#pragma unroll
        for (int kn = 0; kn < 8; kn++) {
            acc[t][kn][0] = __expf(acc[t][kn][0] - mA); sA += acc[t][kn][0];
            acc[t][kn][1] = __expf(acc[t][kn][1] - mA); sA += acc[t][kn][1];
            acc[t][kn][2] = __expf(acc[t][kn][2] - mB); sB += acc[t][kn][2];
            acc[t][kn][3] = __expf(acc[t][kn][3] - mB); sB += acc[t][kn][3];
        }
        sA += __shfl_xor_sync(0xffffffffu, sA, 1);
        sA += __shfl_xor_sync(0xffffffffu, sA, 2);
        sB += __shfl_xor_sync(0xffffffffu, sB, 1);
        sB += __shfl_xor_sync(0xffffffffu, sB, 2);
        const float invA = 1.0f / sA, invB = 1.0f / sB;
#pragma unroll
        for (int kn = 0; kn < 8; kn++) {
            int c0 = kn * 8 + 2 * q;
            ms[c0 * MS_PITCH + prow]           = acc[t][kn][0] * invA;
            ms[(c0 + 1) * MS_PITCH + prow]     = acc[t][kn][1] * invA;
            ms[c0 * MS_PITCH + prow + 8]       = acc[t][kn][2] * invB;
            ms[(c0 + 1) * MS_PITCH + prow + 8] = acc[t][kn][3] * invB;
        }
    }
    // stage img tile
    for (int i = tid; i < 3 * TP; i += NT)
        imgs[i] = img[(size_t)b * 3 * HW + (size_t)(i >> 7) * HW + p0 + (i & 127)];
    __syncthreads();

    // coalesced mask store
    {
        float* gm = g_mask + (size_t)b * KK * HW + p0;
        for (int i = tid; i < KK * TP; i += NT) {
            int k = i >> 7, px = i & 127;
            gm[(size_t)k * HW + px] = ms[k * MS_PITCH + px];
        }
    }

    // per-CTA partial reductions: thread = (k, half)
    {
        const int k    = tid & 63;
        const int half = tid >> 6;
        const int px0  = half * 64;
        float s = 0.f, mx = -1e30f, c0 = 0.f, c1 = 0.f, c2 = 0.f;
        const float* mrow = ms + k * MS_PITCH + px0;
#pragma unroll 4
        for (int j = 0; j < 64; j++) {
            float mv = mrow[j];
            s += mv;
            mx = fmaxf(mx, mv);
            c0 = fmaf(mv, imgs[px0 + j],       c0);
            c1 = fmaf(mv, imgs[128 + px0 + j], c1);
            c2 = fmaf(mv, imgs[256 + px0 + j], c2);
        }
        __syncthreads();
        if (half == 1) {
            b1s[k * 5 + 0] = s;  b1s[k * 5 + 1] = mx;
            b1s[k * 5 + 2] = c0; b1s[k * 5 + 3] = c1; b1s[k * 5 + 4] = c2;
        }
        __syncthreads();
        if (half == 0) {
            float* gp = g_part + ((size_t)(b * KK + k) * 5) * 512 + cta;
            gp[0 * 512] = s  + b1s[k * 5 + 0];
            gp[1 * 512] = fmaxf(mx, b1s[k * 5 + 1]);
            gp[2 * 512] = c0 + b1s[k * 5 + 2];
            gp[3 * 512] = c1 + b1s[k * 5 + 3];
            gp[4 * 512] = c2 + b1s[k * 5 + 4];
        }
    }
}

// ---------------------------------------------------------------
// K2: fold 512 per-CTA partials per (b,k)
// ---------------------------------------------------------------
__global__ __launch_bounds__(256)
void k_reduce2()
{
    __shared__ float smr[256];
    const int bk = blockIdx.x;
    const int b = bk >> 6, k = bk & 63;
    const int t = threadIdx.x;
    const float* gp = g_part + (size_t)bk * 5 * 512;

    float r[5];
#pragma unroll
    for (int comp = 0; comp < 5; comp++) {
        float v;
        if (comp == 1) {
            v = fmaxf(gp[comp * 512 + t], gp[comp * 512 + t + 256]);
            smr[t] = v; __syncthreads();
            for (int st = 128; st > 0; st >>= 1) {
                if (t < st) smr[t] = fmaxf(smr[t], smr[t + st]);
                __syncthreads();
            }
        } else {
            v = gp[comp * 512 + t] + gp[comp * 512 + t + 256];
            smr[t] = v; __syncthreads();
            for (int st = 128; st > 0; st >>= 1) {
                if (t < st) smr[t] += smr[t + st];
                __syncthreads();
            }
        }
        r[comp] = smr[0]; __syncthreads();
    }
    if (t == 0) {
        const float invhw = 1.0f / (float)HW;
        g_bkmean[bk] = r[0] * invhw;
        g_bkmax[bk]  = r[1];
        g_wc[(b * 3 + 0) * KK + k] = r[2] * invhw;
        g_wc[(b * 3 + 1) * KK + k] = r[3] * invhw;
        g_wc[(b * 3 + 2) * KK + k] = r[4] * invhw;
    }
}

// ---------------------------------------------------------------
// K3: scalar outputs
// ---------------------------------------------------------------
__global__ void k_final(float* __restrict__ out)
{
    __shared__ float smr[512];
    __shared__ float bmean[NB], bstd[NB];
    const int t = threadIdx.x;

    smr[t] = g_bkmax[t]; __syncthreads();
    for (int st = 256; st > 0; st >>= 1) { if (t < st) smr[t] += smr[t + st]; __syncthreads(); }
    if (t == 0) out[(size_t)NB * 3 * HW] = smr[0] * (1.0f / 512.0f);
    __syncthreads();

    const float mv = g_bkmean[t];
    smr[t] = mv; __syncthreads();
    if (t < NB) {
        float sbm = 0.f;
        for (int k = 0; k < KK; k++) sbm += smr[t * KK + k];
        bmean[t] = sbm * (1.0f / KK);
    }
    __syncthreads();
    const float d = mv - bmean[t >> 6];
    smr[t] = d * d; __syncthreads();
    if (t < NB) {
        float sbm = 0.f;
        for (int k = 0; k < KK; k++) sbm += smr[t * KK + k];
        bstd[t] = sqrtf(sbm / (float)(KK - 1));
    }
    __syncthreads();
    if (t == 0) {
        float sbm = 0.f;
        for (int bb = 0; bb < NB; bb++) sbm += bstd[bb];
        out[(size_t)NB * 3 * HW + 1] = sbm * (1.0f / NB);
    }
}

// ---------------------------------------------------------------
// K4: transformed_img[b,c,p] = sum_k mask[b,k,p] * wc[b,c,k]
// ---------------------------------------------------------------
__global__ __launch_bounds__(256)
void k_transform(float* __restrict__ out)
{
    __shared__ float wcs[3 * KK];
    const int b = blockIdx.x >> 8;
    const int p = ((blockIdx.x & 255) << 8) + threadIdx.x;
    if (threadIdx.x < 3 * KK) wcs[threadIdx.x] = g_wc[b * 3 * KK + threadIdx.x];
    __syncthreads();

    const float* gm = g_mask + (size_t)b * KK * HW + p;
    float o0 = 0.f, o1 = 0.f, o2 = 0.f;
#pragma unroll
    for (int k = 0; k < KK; k++) {
        const float mv = __ldcs(&gm[(size_t)k * HW]);
        o0 = fmaf(mv, wcs[k],          o0);
        o1 = fmaf(mv, wcs[KK + k],     o1);
        o2 = fmaf(mv, wcs[2 * KK + k], o2);
    }
    out[((size_t)b * 3 + 0) * HW + p] = o0;
    out[((size_t)b * 3 + 1) * HW + p] = o1;
    out[((size_t)b * 3 + 2) * HW + p] = o2;
}

// ---------------------------------------------------------------
extern "C" void kernel_launch(void* const* d_in, const int* in_sizes, int n_in,
                              void* d_out, int out_size)
{
    const float* img  = (const float*)d_in[0];
    const float* feat = (const float*)d_in[1];
    // d_in[2] = coord_map (unused)
    const float* w1 = (const float*)d_in[3];
    const float* b1 = (const float*)d_in[4];
    const float* w2 = (const float*)d_in[5];
    const float* b2 = (const float*)d_in[6];
    float* out = (float*)d_out;

    cudaFuncSetAttribute(k_mask, cudaFuncAttributeMaxDynamicSharedMemorySize, SMEM_REQ);

    k_prep<<<128, 256>>>(w1, w2);
    k_mask<<<NB * (HW / TP), NT, SMEM_REQ>>>(feat, img, b1, b2);
    k_reduce2<<<NB * KK, 256>>>();
    k_final<<<1, 512>>>(out);
    k_transform<<<NB * (HW / 256), 256>>>(out);
}